// round 3
// baseline (speedup 1.0000x reference)
#include <cuda_runtime.h>
#include <cuda_bf16.h>
#include <math.h>
#include <stdint.h>

#define NB 8
#define NS 512
#define ND 1024
#define NO 1024
#define NT 12
#define NL 8
#define NM 4096
#define NK96 96
#define NDEC 48      // 36 dec cols + 12 gate cols
#define NCH 8        // scan chunks
#define CH  64       // chunk length

// ---------------- scratch (static device globals) ---------------------------
__device__ float g_Z[NM*ND];
__device__ float g_outpre[NM*NO];
__device__ float g_dec[NM*NDEC];
__device__ float g_part[NB*NCH*ND];
__device__ float g_pow[NS];
__device__ float g_alpha[NS];
__device__ __nv_bfloat16 g_xhi[NM*ND],     g_xlo[NM*ND];
__device__ __nv_bfloat16 g_cWThi[ND*ND],   g_cWTlo[ND*ND];      // [N=1024][K=1024]
__device__ __nv_bfloat16 g_dWhi[36*ND],    g_dWlo[36*ND];       // [36][1024] (already n-major)
__device__ __nv_bfloat16 g_gWThi[NT*ND],   g_gWTlo[NT*ND];      // [12][1024]
__device__ __nv_bfloat16 g_leafThi[NO*NK96], g_leafTlo[NO*NK96];// [1024][96]
__device__ __nv_bfloat16 g_routhi[NM*ND],  g_routlo[NM*ND];
__device__ __nv_bfloat16 g_coeffhi[NM*NK96], g_coefflo[NM*NK96];

// ---------------- init: powers / alpha ---------------------------------------
__global__ void init_pows_kernel() {
    int s = blockIdx.x * blockDim.x + threadIdx.x;
    if (s < NS) {
        float p = (float)pow(0.9, (double)s);
        g_pow[s]   = p;
        g_alpha[s] = 0.1f / (p + 1e-8f);
    }
}

// ---------------- bf16 hi/lo split helpers -----------------------------------
__device__ __forceinline__ void split_bf16(float v, __nv_bfloat16& h, __nv_bfloat16& l) {
    h = __float2bfloat16(v);
    l = __float2bfloat16(v - __bfloat162float(h));
}

__global__ void split_kernel(const float* __restrict__ src,
                             __nv_bfloat16* __restrict__ hi,
                             __nv_bfloat16* __restrict__ lo, int n) {
    int i = blockIdx.x * blockDim.x + threadIdx.x;
    if (i < n) {
        __nv_bfloat16 h, l;
        split_bf16(src[i], h, l);
        hi[i] = h; lo[i] = l;
    }
}

// transpose + split: src [K][N] fp32 row-major -> dst [N][K] bf16 hi/lo
__global__ void tsplit_kernel(const float* __restrict__ src,
                              __nv_bfloat16* __restrict__ hi,
                              __nv_bfloat16* __restrict__ lo, int K, int N) {
    __shared__ float t[32][33];
    int kb = blockIdx.y * 32, nb = blockIdx.x * 32;
    int tx = threadIdx.x, ty = threadIdx.y;   // 32 x 8
#pragma unroll
    for (int i = 0; i < 32; i += 8) {
        int k = kb + ty + i, n = nb + tx;
        t[ty + i][tx] = (k < K && n < N) ? src[(size_t)k * N + n] : 0.f;
    }
    __syncthreads();
#pragma unroll
    for (int i = 0; i < 32; i += 8) {
        int n = nb + ty + i, k = kb + tx;
        if (n < N && k < K) {
            __nv_bfloat16 h, l;
            split_bf16(t[tx][ty + i], h, l);
            hi[(size_t)n * K + k] = h;
            lo[(size_t)n * K + k] = l;
        }
    }
}

// ---------------- mma / ldmatrix wrappers -------------------------------------
__device__ __forceinline__ void ldsm_x4(uint32_t* d, uint32_t addr) {
    asm volatile("ldmatrix.sync.aligned.m8n8.x4.shared.b16 {%0,%1,%2,%3}, [%4];"
                 : "=r"(d[0]), "=r"(d[1]), "=r"(d[2]), "=r"(d[3]) : "r"(addr));
}
__device__ __forceinline__ void ldsm_x2(uint32_t* d, uint32_t addr) {
    asm volatile("ldmatrix.sync.aligned.m8n8.x2.shared.b16 {%0,%1}, [%2];"
                 : "=r"(d[0]), "=r"(d[1]) : "r"(addr));
}
__device__ __forceinline__ void mma16816(float* c, const uint32_t* a, const uint32_t* b) {
    asm volatile("mma.sync.aligned.m16n8k16.row.col.f32.bf16.bf16.f32 "
                 "{%0,%1,%2,%3}, {%4,%5,%6,%7}, {%8,%9}, {%0,%1,%2,%3};"
                 : "+f"(c[0]), "+f"(c[1]), "+f"(c[2]), "+f"(c[3])
                 : "r"(a[0]), "r"(a[1]), "r"(a[2]), "r"(a[3]), "r"(b[0]), "r"(b[1]));
}

// ---------------- bf16x2 error-compensated GEMM --------------------------------
// C[m, col_ofs+n] = sum_k A[m][k]*B[n][k]   (A: [M][K] row-major hi/lo bf16,
//                                            B: [Nreal][K] row-major hi/lo bf16)
// Computes hi*hi + hi*lo + lo*hi in fp32 accumulators.
template<int WARPS_M, int WARPS_N, int WM_T, int WN_T>
__global__ __launch_bounds__(256, 1)
void gemm_bf16x2(const __nv_bfloat16* __restrict__ Ahi, const __nv_bfloat16* __restrict__ Alo,
                 const __nv_bfloat16* __restrict__ Bhi, const __nv_bfloat16* __restrict__ Blo,
                 float* __restrict__ C, int K, int Nreal, int ldc, int col_ofs)
{
    constexpr int BM = WARPS_M * WM_T * 16;
    constexpr int BN = WARPS_N * WN_T * 8;
    constexpr int LD = 40;   // bf16 elems per smem row (32 + 8 pad -> conflict-free ldsm)
    __shared__ __nv_bfloat16 sAh[BM * LD], sAl[BM * LD];
    __shared__ __nv_bfloat16 sBh[BN * LD], sBl[BN * LD];

    int tid  = threadIdx.x;
    int warp = tid >> 5, lane = tid & 31;
    int wm = warp / WARPS_N, wn = warp % WARPS_N;
    int row0 = blockIdx.y * BM;
    int n0   = blockIdx.x * BN;

    float acc[WM_T][WN_T][4];
#pragma unroll
    for (int i = 0; i < WM_T; i++)
#pragma unroll
        for (int j = 0; j < WN_T; j++)
#pragma unroll
            for (int q = 0; q < 4; q++) acc[i][j][q] = 0.f;

    int g = lane >> 3, r = lane & 7;
    int lrw = tid >> 2;             // 0..63, loader row
    int lsg = (tid & 3) * 8;        // 0/8/16/24, loader k segment

    for (int k0 = 0; k0 < K; k0 += 32) {
        // ---- stage A tile [BM][32] ----
#pragma unroll
        for (int p = 0; p < BM; p += 64) {
            const __nv_bfloat16* sh = Ahi + (size_t)(row0 + lrw + p) * K + k0 + lsg;
            const __nv_bfloat16* sl = Alo + (size_t)(row0 + lrw + p) * K + k0 + lsg;
            *reinterpret_cast<uint4*>(sAh + (lrw + p) * LD + lsg) = *reinterpret_cast<const uint4*>(sh);
            *reinterpret_cast<uint4*>(sAl + (lrw + p) * LD + lsg) = *reinterpret_cast<const uint4*>(sl);
        }
        // ---- stage B tile [BN][32] (guard Nreal rows) ----
#pragma unroll
        for (int p = 0; p < BN; p += 64) {
            int n = n0 + lrw + p;
            uint4 vh = make_uint4(0u, 0u, 0u, 0u), vl = vh;
            if (n < Nreal) {
                vh = *reinterpret_cast<const uint4*>(Bhi + (size_t)n * K + k0 + lsg);
                vl = *reinterpret_cast<const uint4*>(Blo + (size_t)n * K + k0 + lsg);
            }
            *reinterpret_cast<uint4*>(sBh + (lrw + p) * LD + lsg) = vh;
            *reinterpret_cast<uint4*>(sBl + (lrw + p) * LD + lsg) = vl;
        }
        __syncthreads();

#pragma unroll
        for (int ks = 0; ks < 2; ++ks) {
            uint32_t ah[WM_T][4], al[WM_T][4], bh[WN_T][2], bl[WN_T][2];
#pragma unroll
            for (int mt = 0; mt < WM_T; ++mt) {
                int arow = (wm * WM_T + mt) * 16 + (g & 1) * 8 + r;
                int akof = ks * 16 + (g >> 1) * 8;
                uint32_t ah_addr = (uint32_t)__cvta_generic_to_shared(sAh + arow * LD + akof);
                uint32_t al_addr = (uint32_t)__cvta_generic_to_shared(sAl + arow * LD + akof);
                ldsm_x4(ah[mt], ah_addr);
                ldsm_x4(al[mt], al_addr);
            }
            int lm = lane & 15;
#pragma unroll
            for (int nt = 0; nt < WN_T; ++nt) {
                int brow = (wn * WN_T + nt) * 8 + (lm & 7);
                int bkof = ks * 16 + (lm >> 3) * 8;
                uint32_t bh_addr = (uint32_t)__cvta_generic_to_shared(sBh + brow * LD + bkof);
                uint32_t bl_addr = (uint32_t)__cvta_generic_to_shared(sBl + brow * LD + bkof);
                ldsm_x2(bh[nt], bh_addr);
                ldsm_x2(bl[nt], bl_addr);
            }
#pragma unroll
            for (int mt = 0; mt < WM_T; ++mt)
#pragma unroll
                for (int nt = 0; nt < WN_T; ++nt) {
                    mma16816(acc[mt][nt], ah[mt], bh[nt]);
                    mma16816(acc[mt][nt], ah[mt], bl[nt]);
                    mma16816(acc[mt][nt], al[mt], bh[nt]);
                }
        }
        __syncthreads();
    }

    // ---- epilogue ----
#pragma unroll
    for (int mt = 0; mt < WM_T; ++mt) {
        int m = row0 + (wm * WM_T + mt) * 16 + (lane >> 2);
#pragma unroll
        for (int nt = 0; nt < WN_T; ++nt) {
            int nb = n0 + (wn * WN_T + nt) * 8 + (lane & 3) * 2;
            float* crow0 = C + (size_t)m * ldc + col_ofs;
            float* crow1 = C + (size_t)(m + 8) * ldc + col_ofs;
            if (nb < Nreal)     { crow0[nb]     = acc[mt][nt][0]; crow1[nb]     = acc[mt][nt][2]; }
            if (nb + 1 < Nreal) { crow0[nb + 1] = acc[mt][nt][1]; crow1[nb + 1] = acc[mt][nt][3]; }
        }
    }
}

// ---------------- EMA chunked scan ---------------------------------------------
// part[b][c][d] = sum_{s in chunk c, s>=1} pow[s] * Z[b][s-1][d]
__global__ __launch_bounds__(256)
void emaP1_kernel() {
    int b = blockIdx.x, c = blockIdx.y;
    int d = blockIdx.z * blockDim.x + threadIdx.x;
    const float* Zb = g_Z + (size_t)b * NS * ND + d;
    float s = 0.f;
    int s0 = c * CH;
#pragma unroll 4
    for (int i = 0; i < CH; ++i) {
        int sidx = s0 + i;
        if (sidx > 0) s = fmaf(g_pow[sidx], Zb[(size_t)(sidx - 1) * ND], s);
    }
    g_part[((size_t)b * NCH + c) * ND + d] = s;
}

// routing = x + alpha_s * prefix + cb, split to bf16 hi/lo
__global__ __launch_bounds__(256)
void emaP2_kernel(const float* __restrict__ x, const float* __restrict__ cb) {
    int b = blockIdx.x, c = blockIdx.y;
    int d = blockIdx.z * blockDim.x + threadIdx.x;
    float acc = 0.f;
    for (int cc = 0; cc < c; ++cc) acc += g_part[((size_t)b * NCH + cc) * ND + d];
    const float* Zb = g_Z + (size_t)b * NS * ND + d;
    const float* xb = x   + (size_t)b * NS * ND + d;
    __nv_bfloat16* rh = g_routhi + (size_t)b * NS * ND + d;
    __nv_bfloat16* rl = g_routlo + (size_t)b * NS * ND + d;
    float bias = cb[d];
    int s0 = c * CH;
#pragma unroll 4
    for (int i = 0; i < CH; ++i) {
        int sidx = s0 + i;
        float zprev = (sidx > 0) ? Zb[(size_t)(sidx - 1) * ND] : 0.f;
        acc = fmaf(g_pow[sidx], zprev, acc);
        float rv = xb[(size_t)sidx * ND] + g_alpha[sidx] * acc + bias;
        __nv_bfloat16 h, l;
        split_bf16(rv, h, l);
        rh[(size_t)sidx * ND] = h;
        rl[(size_t)sidx * ND] = l;
    }
}

// ---------------- coeff: sigmoid / softmax / kron -> bf16 hi/lo -----------------
__global__ __launch_bounds__(256)
void coeff_kernel(const float* __restrict__ db, const float* __restrict__ gb,
                  const float* __restrict__ ntl) {
    __shared__ float sItv[36];
    int tid = threadIdx.x;
    if (tid < 36) {
        float v  = ntl[tid] + 0.5413f;
        float sp = (v > 20.f) ? v : log1pf(expf(v));
        sItv[tid] = 1.f / sp;
    }
    __syncthreads();
    int row = blockIdx.x * blockDim.x + tid;
    const float* dd = g_dec + (size_t)row * NDEC;
    float sg[36];
#pragma unroll
    for (int j = 0; j < 36; ++j) {
        float v = (dd[j] + db[j]) * sItv[j];
        sg[j] = 1.f / (1.f + expf(-v));
    }
    float gv[12], mx = -1e30f;
#pragma unroll
    for (int t = 0; t < 12; ++t) { gv[t] = dd[36 + t] + gb[t]; mx = fmaxf(mx, gv[t]); }
    float es = 0.f;
#pragma unroll
    for (int t = 0; t < 12; ++t) { gv[t] = expf(gv[t] - mx); es += gv[t]; }
    float inv = 1.f / es;
    __nv_bfloat16* ch = g_coeffhi + (size_t)row * NK96;
    __nv_bfloat16* cl = g_coefflo + (size_t)row * NK96;
#pragma unroll
    for (int t = 0; t < 12; ++t) {
        float w  = gv[t] * inv;
        float a0 = sg[3 * t], a1 = sg[3 * t + 1], a2 = sg[3 * t + 2];
        float q0[2] = {a0, 1.f - a0};
        float q1[2] = {a1, 1.f - a1};
        float q2[2] = {a2, 1.f - a2};
#pragma unroll
        for (int i0 = 0; i0 < 2; i0++)
#pragma unroll
            for (int i1 = 0; i1 < 2; i1++)
#pragma unroll
                for (int i2 = 0; i2 < 2; i2++) {
                    __nv_bfloat16 h, l;
                    split_bf16(w * q0[i0] * q1[i1] * q2[i2], h, l);
                    int idx = t * 8 + i0 * 4 + i1 * 2 + i2;
                    ch[idx] = h; cl[idx] = l;
                }
    }
}

// ---------------- LayerNorm ------------------------------------------------------
__global__ __launch_bounds__(256)
void ln_kernel(const float* __restrict__ gamma, const float* __restrict__ beta,
               float* __restrict__ out) {
    __shared__ float sh[8];
    int row = blockIdx.x;
    int tid = threadIdx.x;
    const float* p = g_outpre + (size_t)row * NO;
    float4 v = *reinterpret_cast<const float4*>(p + tid * 4);

    float s = v.x + v.y + v.z + v.w;
#pragma unroll
    for (int o = 16; o > 0; o >>= 1) s += __shfl_xor_sync(0xffffffffu, s, o);
    if ((tid & 31) == 0) sh[tid >> 5] = s;
    __syncthreads();
    if (tid == 0) {
        float t2 = 0.f;
#pragma unroll
        for (int i = 0; i < 8; i++) t2 += sh[i];
        sh[0] = t2;
    }
    __syncthreads();
    float mu = sh[0] * (1.f / 1024.f);
    __syncthreads();

    float dx = v.x - mu, dy = v.y - mu, dz = v.z - mu, dw = v.w - mu;
    float sq = dx * dx + dy * dy + dz * dz + dw * dw;
#pragma unroll
    for (int o = 16; o > 0; o >>= 1) sq += __shfl_xor_sync(0xffffffffu, sq, o);
    if ((tid & 31) == 0) sh[tid >> 5] = sq;
    __syncthreads();
    if (tid == 0) {
        float t2 = 0.f;
#pragma unroll
        for (int i = 0; i < 8; i++) t2 += sh[i];
        sh[0] = t2;
    }
    __syncthreads();
    float var  = sh[0] * (1.f / 1024.f);
    float rstd = rsqrtf(var + 1e-5f);

    float4 gm = *reinterpret_cast<const float4*>(gamma + tid * 4);
    float4 bt = *reinterpret_cast<const float4*>(beta + tid * 4);
    float4 o4;
    o4.x = dx * rstd * gm.x + bt.x;
    o4.y = dy * rstd * gm.y + bt.y;
    o4.z = dz * rstd * gm.z + bt.z;
    o4.w = dw * rstd * gm.w + bt.w;
    *reinterpret_cast<float4*>(out + (size_t)row * NO + tid * 4) = o4;
}

// ---------------- launch ----------------------------------------------------------
extern "C" void kernel_launch(void* const* d_in, const int* in_sizes, int n_in,
                              void* d_out, int out_size) {
    (void)in_sizes; (void)n_in; (void)out_size;
    const float* x     = (const float*)d_in[0];
    const float* cW    = (const float*)d_in[1];
    const float* cb    = (const float*)d_in[2];
    const float* dW    = (const float*)d_in[3];
    const float* db    = (const float*)d_in[4];
    const float* leaf  = (const float*)d_in[5];
    const float* gW    = (const float*)d_in[6];
    const float* gb    = (const float*)d_in[7];
    const float* ntl   = (const float*)d_in[8];
    const float* gamma = (const float*)d_in[9];
    const float* beta  = (const float*)d_in[10];
    float* out = (float*)d_out;

    float *Z, *outpre, *dec;
    __nv_bfloat16 *xhi, *xlo, *cWThi, *cWTlo, *dWhi, *dWlo, *gWThi, *gWTlo;
    __nv_bfloat16 *leafThi, *leafTlo, *routhi, *routlo, *coeffhi, *coefflo;
    cudaGetSymbolAddress((void**)&Z,       g_Z);
    cudaGetSymbolAddress((void**)&outpre,  g_outpre);
    cudaGetSymbolAddress((void**)&dec,     g_dec);
    cudaGetSymbolAddress((void**)&xhi,     g_xhi);
    cudaGetSymbolAddress((void**)&xlo,     g_xlo);
    cudaGetSymbolAddress((void**)&cWThi,   g_cWThi);
    cudaGetSymbolAddress((void**)&cWTlo,   g_cWTlo);
    cudaGetSymbolAddress((void**)&dWhi,    g_dWhi);
    cudaGetSymbolAddress((void**)&dWlo,    g_dWlo);
    cudaGetSymbolAddress((void**)&gWThi,   g_gWThi);
    cudaGetSymbolAddress((void**)&gWTlo,   g_gWTlo);
    cudaGetSymbolAddress((void**)&leafThi, g_leafThi);
    cudaGetSymbolAddress((void**)&leafTlo, g_leafTlo);
    cudaGetSymbolAddress((void**)&routhi,  g_routhi);
    cudaGetSymbolAddress((void**)&routlo,  g_routlo);
    cudaGetSymbolAddress((void**)&coeffhi, g_coeffhi);
    cudaGetSymbolAddress((void**)&coefflo, g_coefflo);

    init_pows_kernel<<<2, 256>>>();
    // operand preparation: split / transpose-split to bf16 hi/lo
    split_kernel<<<(NM * ND + 255) / 256, 256>>>(x, xhi, xlo, NM * ND);
    tsplit_kernel<<<dim3(ND / 32, ND / 32), dim3(32, 8)>>>(cW, cWThi, cWTlo, ND, ND);       // [1024][1024] -> [1024][1024]
    split_kernel<<<(36 * ND + 255) / 256, 256>>>(dW, dWhi, dWlo, 36 * ND);                  // dW already [36][1024]
    tsplit_kernel<<<dim3(1, ND / 32), dim3(32, 8)>>>(gW, gWThi, gWTlo, ND, NT);             // [1024][12] -> [12][1024]
    tsplit_kernel<<<dim3(NO / 32, 3), dim3(32, 8)>>>(leaf, leafThi, leafTlo, NK96, NO);     // [96][1024] -> [1024][96]

    // GEMM1: Z = x @ cW   (tensor, bf16x2)
    gemm_bf16x2<2, 4, 4, 4><<<dim3(ND / 128, NM / 128), 256>>>(
        xhi, xlo, cWThi, cWTlo, Z, ND, ND, ND, 0);
    // EMA chunked scan -> routing (bf16 hi/lo)
    emaP1_kernel<<<dim3(NB, NCH, ND / 256), 256>>>();
    emaP2_kernel<<<dim3(NB, NCH, ND / 256), 256>>>(x, cb);
    // dec = routing @ dW^T -> cols 0..35 ; gate = x @ gW -> cols 36..47
    gemm_bf16x2<4, 2, 2, 4><<<dim3(1, NM / 128), 256>>>(
        routhi, routlo, dWhi, dWlo, dec, ND, 36, NDEC, 0);
    gemm_bf16x2<4, 2, 2, 4><<<dim3(1, NM / 128), 256>>>(
        xhi, xlo, gWThi, gWTlo, dec, ND, NT, NDEC, 36);
    // coeff = w_t * leaf_probs -> bf16 hi/lo
    coeff_kernel<<<NM / 256, 256>>>(db, gb, ntl);
    // outpre = coeff @ leaf_out
    gemm_bf16x2<2, 4, 4, 4><<<dim3(NO / 128, NM / 128), 256>>>(
        coeffhi, coefflo, leafThi, leafTlo, outpre, NK96, NO, NO, 0);
    // LayerNorm
    ln_kernel<<<NM, 256>>>(gamma, beta, out);
}